// round 17
// baseline (speedup 1.0000x reference)
#include <cuda_runtime.h>

#define BB 16384
#define NSITES 784
#define OO 10
#define LABEL 392
#define NPAIR 74
#define NTHR 112
#define NGRP 195
#define TAU2 144.0                       // gate: rho^2 <= 144 (rho <= 12)
#define TLF (NGRP*256 + 128)             // left table: pair slots + classic site 391
#define TRF (NGRP*256)
#define FLG_OFF (NGRP*256 + 128)         // flags (ints) in smem after table
#define SWFL (FLG_OFF + 200)

typedef unsigned long long u64;

__device__ __forceinline__ u64 pk2(float a, float b) {
    u64 r; asm("mov.b64 %0, {%1, %2};" : "=l"(r) : "f"(a), "f"(b)); return r;
}
__device__ __forceinline__ void upk2(float& a, float& b, u64 r) {
    asm("mov.b64 {%0, %1}, %2;" : "=f"(a), "=f"(b) : "l"(r));
}
__device__ __forceinline__ u64 fma2(u64 a, u64 b, u64 c) {
    u64 d; asm("fma.rn.f32x2 %0, %1, %2, %3;" : "=l"(d) : "l"(a), "l"(b), "l"(c)); return d;
}
__device__ __forceinline__ u64 mul2(u64 a, u64 b) {
    u64 d; asm("mul.rn.f32x2 %0, %1, %2;" : "=l"(d) : "l"(a), "l"(b)); return d;
}

// pair slot (256 floats): good: [Cb1|G|Cb2|-]  bad: [A1|C1|A2|C2]
__device__ __align__(16) float g_TL[TLF];
__device__ __align__(16) float g_TR[TRF];
__device__ int g_pfL[NGRP];
__device__ int g_pfR[NGRP];
__device__ __align__(8)  float g_Alab[640];
__device__ __align__(8)  float g_Clab[640];
__device__ float g_w0c[16];
__device__ float g_wlastc[16];
__device__ __align__(16) float g_vleft[BB * 8];
__device__ __align__(16) float g_u[BB * 8];
__device__ unsigned g_flag[NPAIR];

// ---------------- fp64 helpers (64 threads) ----------------
__device__ void mmul8(double* d, const double* a, const double* b, int r, int c) {
    __syncthreads();
    double s = 0.0;
    #pragma unroll
    for (int k = 0; k < 8; k++) s += a[r*8+k] * b[k*8+c];
    __syncthreads();
    d[r*8+c] = s;
    __syncthreads();
}
__device__ void minv8(double* dst, const double* src, double* W, int* piv,
                      int r, int c, int tid) {
    __syncthreads();
    W[r*16+c] = src[r*8+c];
    W[r*16+8+c] = (r == c) ? 1.0 : 0.0;
    __syncthreads();
    for (int k = 0; k < 8; k++) {
        if (tid == 0) {
            int best = k; double bv = fabs(W[k*16+k]);
            for (int rr = k+1; rr < 8; rr++) {
                double t = fabs(W[rr*16+k]);
                if (t > bv) { bv = t; best = rr; }
            }
            *piv = best;
        }
        __syncthreads();
        int pr = *piv;
        if (pr != k && r == 0) {
            double t0 = W[k*16+c];   W[k*16+c]   = W[pr*16+c];   W[pr*16+c]   = t0;
            double t1 = W[k*16+8+c]; W[k*16+8+c] = W[pr*16+8+c]; W[pr*16+8+c] = t1;
        }
        __syncthreads();
        double pv = W[k*16+k];
        __syncthreads();
        if (r == k) { W[r*16+c] /= pv; W[r*16+8+c] /= pv; }
        __syncthreads();
        double f = W[r*16+k], pa = W[k*16+c], pb = W[k*16+8+c];
        __syncthreads();
        if (r != k) { W[r*16+c] -= f*pa; W[r*16+8+c] -= f*pb; }
        __syncthreads();
    }
    dst[r*8+c] = W[r*16+8+c];
    __syncthreads();
}

__global__ void prep_groups(const float* __restrict__ wl, const float* __restrict__ wr) {
    __shared__ double M[6][64];          // A1,C1,A2,C2,A1i,A2i
    __shared__ double T1[64], T2[64], W[128];
    __shared__ int s_piv, s_flag;
    const int side = blockIdx.x / NGRP, g = blockIdx.x % NGRP;
    const int tid = threadIdx.x, r = tid >> 3, c = tid & 7;

    for (int t = 0; t < 2; t++) {
        double a, cc;
        if (side == 0) {                 // left pair g: wl idx 2g+t
            const float* base = wl + (size_t)(2*g + t) * 128;
            a = (double)base[r*16 + c];
            cc = (double)base[r*16 + 8 + c] - a;
        } else {                         // right pair g: wr local 389-2g-t, transposed
            const float* base = wr + (size_t)(389 - 2*g - t) * 128;
            a = (double)base[c*16 + r];
            cc = (double)base[c*16 + 8 + r] - a;
        }
        M[2*t][r*8+c] = a; M[2*t+1][r*8+c] = cc;
    }
    minv8(M[4], M[0], W, &s_piv, r, c, tid);   // A1i
    minv8(M[5], M[2], W, &s_piv, r, c, tid);   // A2i
    mmul8(T1, M[1], M[4], r, c);               // Cb1 = C1*A1i
    mmul8(T2, M[5], M[3], r, c);               // Cb2 = A2i*C2
    if (tid == 0) {
        double n1 = 0, d1 = 0, n2 = 0, d2 = 0;
        for (int i = 0; i < 64; i++) {
            n1 += T1[i]*T1[i]; d1 += M[1][i]*M[1][i];
            n2 += T2[i]*T2[i]; d2 += M[3][i]*M[3][i];
        }
        s_flag = (n1 <= TAU2 * d1 && n2 <= TAU2 * d2) ? 1 : 0;
    }
    mmul8(W, M[0], M[2], r, c);                // G = A1*A2 (also syncs s_flag)
    float* out = (side == 0 ? g_TL : g_TR) + g * 256;
    if (s_flag) {
        out[r*8+c]       = (float)T1[r*8+c];
        out[64 + r*8+c]  = (float)W[r*8+c];
        out[128 + r*8+c] = (float)T2[r*8+c];
    } else {
        out[r*8+c]       = (float)M[0][r*8+c];
        out[64 + r*8+c]  = (float)M[1][r*8+c];
        out[128 + r*8+c] = (float)M[2][r*8+c];
        out[192 + r*8+c] = (float)M[3][r*8+c];
    }
    if (tid == 0) { if (side == 0) g_pfL[g] = s_flag; else g_pfR[g] = s_flag; }
}

__global__ void prep_misc(const float* __restrict__ wl, const float* __restrict__ wlab,
                          const float* __restrict__ w0, const float* __restrict__ wlast) {
    const int tid = threadIdx.x;
    if (tid < 128) {                     // left leftover: site 391 (wl idx 390), classic A|C
        int h = tid >> 6, q = tid & 63, d = q >> 3, e = q & 7;
        const float* base = wl + (size_t)390 * 128;
        float a = base[d*16+e], b = base[d*16+8+e];
        g_TL[NGRP*256 + h*64 + d*8+e] = h ? (b - a) : a;
    }
    for (int i = tid; i < 640; i += 256) {
        int o = i % OO, de = i / OO, e = de & 7, d = de >> 3;
        float a = wlab[(d*16 + e)*OO + o];
        float b = wlab[(d*16 + 8 + e)*OO + o];
        g_Alab[(d*8+e)*OO + o] = a;
        g_Clab[(d*8+e)*OO + o] = b - a;
    }
    if (tid < 8) { g_w0c[tid] = w0[tid]; g_w0c[8+tid] = w0[8+tid] - w0[tid]; }
    else if (tid < 16) {
        int d = tid - 8;
        g_wlastc[d] = wlast[d*2]; g_wlastc[8+d] = wlast[d*2+1] - wlast[d*2];
    }
    if (tid < NPAIR) g_flag[tid] = 0;
}

// ---------------- runtime steps (e-packed, 2 rows) ----------------
#define MV_BODY(q) \
    u64 A0,A1,A2,A3,B0,B1,B2,B3; \
    { u64 x0 = pk2(v0[0],v0[0]), x1 = pk2(v1[0],v1[0]); \
      ulonglong2 qa = q[0], qb = q[1]; \
      A0=mul2(x0,qa.x); A1=mul2(x0,qa.y); A2=mul2(x0,qb.x); A3=mul2(x0,qb.y); \
      B0=mul2(x1,qa.x); B1=mul2(x1,qa.y); B2=mul2(x1,qb.x); B3=mul2(x1,qb.y); } \
    _Pragma("unroll") \
    for (int i = 1; i < 8; i++) { \
      u64 x0 = pk2(v0[i],v0[i]), x1 = pk2(v1[i],v1[i]); \
      ulonglong2 qa = q[2*i], qb = q[2*i+1]; \
      A0=fma2(x0,qa.x,A0); A1=fma2(x0,qa.y,A1); A2=fma2(x0,qb.x,A2); A3=fma2(x0,qb.y,A3); \
      B0=fma2(x1,qa.x,B0); B1=fma2(x1,qa.y,B1); B2=fma2(x1,qb.x,B2); B3=fma2(x1,qb.y,B3); }

__device__ __forceinline__ void gstep(const float* __restrict__ w,
                                      float (&v0)[8], float (&v1)[8]) {
    const ulonglong2* __restrict__ q = (const ulonglong2*)w;
    MV_BODY(q)
    upk2(v0[0],v0[1],A0); upk2(v0[2],v0[3],A1); upk2(v0[4],v0[5],A2); upk2(v0[6],v0[7],A3);
    upk2(v1[0],v1[1],B0); upk2(v1[2],v1[3],B1); upk2(v1[4],v1[5],B2); upk2(v1[6],v1[7],B3);
}
__device__ __forceinline__ void bstep(const float* __restrict__ w,
                                      float (&v0)[8], float (&v1)[8], float p0, float p1) {
    const ulonglong2* __restrict__ q = (const ulonglong2*)w;
    MV_BODY(q)
    u64 pp0 = pk2(p0,p0), pp1 = pk2(p1,p1);
    u64 w0_ = pk2(v0[0],v0[1]), w1_ = pk2(v0[2],v0[3]), w2_ = pk2(v0[4],v0[5]), w3_ = pk2(v0[6],v0[7]);
    u64 y0 = pk2(v1[0],v1[1]), y1 = pk2(v1[2],v1[3]), y2 = pk2(v1[4],v1[5]), y3 = pk2(v1[6],v1[7]);
    w0_ = fma2(pp0,A0,w0_); w1_ = fma2(pp0,A1,w1_); w2_ = fma2(pp0,A2,w2_); w3_ = fma2(pp0,A3,w3_);
    y0 = fma2(pp1,B0,y0); y1 = fma2(pp1,B1,y1); y2 = fma2(pp1,B2,y2); y3 = fma2(pp1,B3,y3);
    upk2(v0[0],v0[1],w0_); upk2(v0[2],v0[3],w1_); upk2(v0[4],v0[5],w2_); upk2(v0[6],v0[7],w3_);
    upk2(v1[0],v1[1],y0); upk2(v1[2],v1[3],y1); upk2(v1[4],v1[5],y2); upk2(v1[6],v1[7],y3);
}
__device__ __forceinline__ void site_step(const float* __restrict__ w,
                                          float (&v0)[8], float (&v1)[8], float p0, float p1) {
    const ulonglong2* __restrict__ q = (const ulonglong2*)w;
    MV_BODY(q)
    const ulonglong2* __restrict__ qc = q + 16;
    u64 C0,C1,C2,C3,D0,D1,D2,D3;
    { u64 x0 = pk2(v0[0],v0[0]), x1 = pk2(v1[0],v1[0]);
      ulonglong2 qa = qc[0], qb = qc[1];
      C0=mul2(x0,qa.x); C1=mul2(x0,qa.y); C2=mul2(x0,qb.x); C3=mul2(x0,qb.y);
      D0=mul2(x1,qa.x); D1=mul2(x1,qa.y); D2=mul2(x1,qb.x); D3=mul2(x1,qb.y); }
    #pragma unroll
    for (int i = 1; i < 8; i++) {
      u64 x0 = pk2(v0[i],v0[i]), x1 = pk2(v1[i],v1[i]);
      ulonglong2 qa = qc[2*i], qb = qc[2*i+1];
      C0=fma2(x0,qa.x,C0); C1=fma2(x0,qa.y,C1); C2=fma2(x0,qb.x,C2); C3=fma2(x0,qb.y,C3);
      D0=fma2(x1,qa.x,D0); D1=fma2(x1,qa.y,D1); D2=fma2(x1,qb.x,D2); D3=fma2(x1,qb.y,D3);
    }
    u64 pp0 = pk2(p0,p0), pp1 = pk2(p1,p1);
    A0=fma2(pp0,C0,A0); A1=fma2(pp0,C1,A1); A2=fma2(pp0,C2,A2); A3=fma2(pp0,C3,A3);
    B0=fma2(pp1,D0,B0); B1=fma2(pp1,D1,B1); B2=fma2(pp1,D2,B2); B3=fma2(pp1,D3,B3);
    upk2(v0[0],v0[1],A0); upk2(v0[2],v0[3],A1); upk2(v0[4],v0[5],A2); upk2(v0[6],v0[7],A3);
    upk2(v1[0],v1[1],B0); upk2(v1[2],v1[3],B1); upk2(v1[4],v1[5],B2); upk2(v1[6],v1[7],B3);
}
// one pair: good = bstep,gstep,bstep ; bad = 2 classic sites
__device__ __forceinline__ void pair_step(const float* __restrict__ slot, int flag,
                                          float (&v0)[8], float (&v1)[8],
                                          float pa0, float pa1, float pb0, float pb1) {
    if (flag) {
        bstep(slot, v0, v1, pa0, pa1);
        gstep(slot + 64, v0, v1);
        bstep(slot + 128, v0, v1, pb0, pb1);
    } else {
        site_step(slot, v0, v1, pa0, pa1);
        site_step(slot + 128, v0, v1, pb0, pb1);
    }
}

__device__ __forceinline__ void label_row(const u64* __restrict__ sA, const u64* __restrict__ sC,
                                          const float (&vl)[8], const float (&uu)[8],
                                          float p, float* __restrict__ out, int row) {
    const u64 p2 = pk2(p, p);
    u64 acc[5] = {0,0,0,0,0};
    #pragma unroll
    for (int d = 0; d < 8; d++) {
        #pragma unroll
        for (int e = 0; e < 8; e++) {
            const float g = vl[d] * uu[e];
            const u64 g2 = pk2(g, g);
            const u64 gp2 = mul2(g2, p2);
            const int base = (d*8 + e) * 5;
            #pragma unroll
            for (int k = 0; k < 5; k++) {
                acc[k] = fma2(g2, sA[base+k], acc[k]);
                acc[k] = fma2(gp2, sC[base+k], acc[k]);
            }
        }
    }
    float2* o2 = (float2*)(out + row * OO);
    #pragma unroll
    for (int k = 0; k < 5; k++) { float lo, hi; upk2(lo, hi, acc[k]); o2[k] = make_float2(lo, hi); }
}

// ---------------- fused chain + label: 148 CTAs x 112 thr x 2 rows ----------------
__global__ __launch_bounds__(NTHR, 1) void chain_kernel(const float* __restrict__ x,
                                                        float* __restrict__ out) {
    extern __shared__ float sw[];
    __shared__ unsigned s_old;
    const int tid = threadIdx.x, blk = blockIdx.x;
    const bool isLeft = blk < NPAIR;
    const int pair = isLeft ? blk : blk - NPAIR;
    int* sflg = (int*)(sw + FLG_OFF);

    {
        const float4* g4 = (const float4*)(isLeft ? g_TL : g_TR);
        float4* s4 = (float4*)sw;
        const int n4 = (isLeft ? TLF : TRF) / 4;
        for (int i = tid; i < n4; i += NTHR) s4[i] = g4[i];
        const int* gf = isLeft ? g_pfL : g_pfR;
        for (int i = tid; i < NGRP; i += NTHR) sflg[i] = gf[i];
    }
    __syncthreads();

    const int slot = pair * NTHR + tid;
    int r0 = slot * 2;
    if (r0 > BB - 2) r0 = BB - 2;
    const int r1 = r0 + 1;
    const float* px0 = x + (size_t)r0 * NSITES;
    const float* px1 = x + (size_t)r1 * NSITES;

    float v0[8], v1[8];
    if (isLeft) {
        float4 f0 = *(const float4*)px0;
        float4 f1 = *(const float4*)px1;
        #pragma unroll
        for (int d = 0; d < 8; d++) {
            v0[d] = fmaf(f0.x, g_w0c[8+d], g_w0c[d]);
            v1[d] = fmaf(f1.x, g_w0c[8+d], g_w0c[d]);
        }
        float4 n0 = *(const float4*)(px0 + 4);
        float4 n1 = *(const float4*)(px1 + 4);
        const float* wp = sw;
        #pragma unroll 1
        for (int q = 0; q <= 96; q++) {           // pairs 2q,2q+1: sites 4q+1..4q+4
            pair_step(wp,       sflg[2*q],   v0, v1, f0.y, f1.y, f0.z, f1.z);
            pair_step(wp + 256, sflg[2*q+1], v0, v1, f0.w, f1.w, n0.x, n1.x);
            wp += 512;
            f0 = n0; f1 = n1;
            n0 = *(const float4*)(px0 + 4*q + 8); // q=96 -> x[392..395], valid
            n1 = *(const float4*)(px1 + 4*q + 8);
        }
        // pair 194: sites 389,390 ; leftover classic site 391 (f0 = px[388..391])
        pair_step(wp, sflg[194], v0, v1, f0.y, f1.y, f0.z, f1.z);
        site_step(wp + 256, v0, v1, f0.w, f1.w);
        float4* d0 = (float4*)(g_vleft + r0 * 8);
        d0[0] = make_float4(v0[0],v0[1],v0[2],v0[3]);
        d0[1] = make_float4(v0[4],v0[5],v0[6],v0[7]);
        float4* d1 = (float4*)(g_vleft + r1 * 8);
        d1[0] = make_float4(v1[0],v1[1],v1[2],v1[3]);
        d1[1] = make_float4(v1[4],v1[5],v1[6],v1[7]);
    } else {
        float4 f0 = *(const float4*)(px0 + 780);
        float4 f1 = *(const float4*)(px1 + 780);
        #pragma unroll
        for (int d = 0; d < 8; d++) {
            v0[d] = fmaf(f0.w, g_wlastc[8+d], g_wlastc[d]);
            v1[d] = fmaf(f1.w, g_wlastc[8+d], g_wlastc[d]);
        }
        float4 n0 = *(const float4*)(px0 + 776);
        float4 n1 = *(const float4*)(px1 + 776);
        const float* wp = sw;
        #pragma unroll 1
        for (int m = 0; m <= 96; m++) {           // pairs 2m,2m+1: sites 782-4m..779-4m
            pair_step(wp,       sflg[2*m],   v0, v1, f0.z, f1.z, f0.y, f1.y);
            pair_step(wp + 256, sflg[2*m+1], v0, v1, f0.x, f1.x, n0.w, n1.w);
            wp += 512;
            f0 = n0; f1 = n1;
            n0 = *(const float4*)(px0 + 772 - 4*m);
            n1 = *(const float4*)(px1 + 772 - 4*m);
        }
        // pair 194: sites 394,393 (f0 = px[392..395])
        pair_step(wp, sflg[194], v0, v1, f0.z, f1.z, f0.y, f1.y);
        float4* d0 = (float4*)(g_u + r0 * 8);
        d0[0] = make_float4(v0[0],v0[1],v0[2],v0[3]);
        d0[1] = make_float4(v0[4],v0[5],v0[6],v0[7]);
        float4* d1 = (float4*)(g_u + r1 * 8);
        d1[0] = make_float4(v1[0],v1[1],v1[2],v1[3]);
        d1[1] = make_float4(v1[4],v1[5],v1[6],v1[7]);
    }

    // ---- handoff: second arriver computes label combine ----
    __threadfence();
    __syncthreads();
    if (tid == 0) s_old = atomicAdd(&g_flag[pair], 1u);
    __syncthreads();
    if (!(s_old & 1)) return;
    __threadfence();

    for (int i = tid; i < 320; i += NTHR) {
        ((u64*)sw)[i]       = ((const u64*)g_Alab)[i];
        ((u64*)sw)[320 + i] = ((const u64*)g_Clab)[i];
    }
    __syncthreads();
    const u64* sA = (const u64*)sw;
    const u64* sC = sA + 320;

    const float* other = isLeft ? g_u : g_vleft;
    #pragma unroll 1
    for (int rr = 0; rr < 2; rr++) {
        const int row = rr == 0 ? r0 : r1;
        float vv[8], oo[8];
        #pragma unroll
        for (int e = 0; e < 8; e++) vv[e] = (rr == 0) ? v0[e] : v1[e];
        const float4* s0 = (const float4*)(other + row * 8);
        float4 a = s0[0], b = s0[1];
        oo[0]=a.x; oo[1]=a.y; oo[2]=a.z; oo[3]=a.w;
        oo[4]=b.x; oo[5]=b.y; oo[6]=b.z; oo[7]=b.w;
        const float pl = x[(size_t)row * NSITES + LABEL];
        if (isLeft) label_row(sA, sC, vv, oo, pl, out, row);
        else        label_row(sA, sC, oo, vv, pl, out, row);
    }
}

extern "C" void kernel_launch(void* const* d_in, const int* in_sizes, int n_in,
                              void* d_out, int out_size) {
    const float* x      = (const float*)d_in[0];
    const float* w0     = (const float*)d_in[1];
    const float* Wleft  = (const float*)d_in[2];
    const float* wlabel = (const float*)d_in[3];
    const float* Wright = (const float*)d_in[4];
    const float* wlast  = (const float*)d_in[5];
    float* out = (float*)d_out;

    const int smemBytes = SWFL * (int)sizeof(float);   // 200,992 B
    cudaFuncSetAttribute(chain_kernel, cudaFuncAttributeMaxDynamicSharedMemorySize, smemBytes);

    prep_groups<<<2 * NGRP, 64>>>(Wleft, Wright);
    prep_misc<<<1, 256>>>(Wleft, wlabel, w0, wlast);
    chain_kernel<<<2 * NPAIR, NTHR, smemBytes>>>(x, out);
}